// round 15
// baseline (speedup 1.0000x reference)
#include <cuda_runtime.h>
#include <cstdint>

// NodePairGaussian: out[b,k,n,m] = clip(exp(-0.1*sqrt(max(|A_n|^2 - 2 A_n.A_m + |A_m|^2, 1e-6))), 0, 1)
// A = x * msk, shapes: x (8,64,512,16) f32, msk (8,64,512,1) f32, out (8,64,512,512,1) f32.

namespace {

constexpr int Fd      = 16;
constexpr int Nn      = 512;
constexpr int SLABS   = 512;   // 8 * 64
constexpr int THREADS = 256;
constexpr float EPSV  = 1e-6f;
constexpr float COEF  = -0.14426950408889634f; // -0.1 * log2(e)

__device__ __forceinline__ unsigned long long dup2(float v) {
    unsigned long long r;
    asm("mov.b64 %0, {%1, %1};" : "=l"(r) : "f"(v));
    return r;
}
__device__ __forceinline__ unsigned long long fma2(unsigned long long a,
                                                   unsigned long long b,
                                                   unsigned long long c) {
    unsigned long long d;
    asm("fma.rn.f32x2 %0, %1, %2, %3;" : "=l"(d) : "l"(a), "l"(b), "l"(c));
    return d;
}
__device__ __forceinline__ float2 unpk(unsigned long long v) {
    float2 r;
    asm("mov.b64 {%0, %1}, %2;" : "=f"(r.x), "=f"(r.y) : "l"(v));
    return r;
}
__device__ __forceinline__ float sqrt_ap(float x) {
    float y; asm("sqrt.approx.f32 %0, %1;" : "=f"(y) : "f"(x)); return y;
}
__device__ __forceinline__ float ex2_ap(float x) {
    float y; asm("ex2.approx.f32 %0, %1;" : "=f"(y) : "f"(x)); return y;
}

__global__ __launch_bounds__(THREADS, 2)
void npg_kernel(const float* __restrict__ x, const float* __restrict__ msk,
                float* __restrict__ out)
{
    // Transposed masked slab: As[f][n], plus squared norms na[n].
    __shared__ float As[Fd][Nn];
    __shared__ float na[Nn];

    const int slab = blockIdx.x >> 2;   // 0..511
    const int quad = blockIdx.x & 3;    // n-quarter (128 rows each)
    const int tid  = threadIdx.x;
    const int tx   = tid & 63;          // m-group: m in {tx*4..+3} and {256+tx*4..+3}
    const int ty   = tid >> 6;          // n-subgroup within a 32-row iteration tile

    const float* xs = x   + (size_t)slab * (Nn * Fd);
    const float* ms = msk + (size_t)slab * Nn;

    // ---- Load slab into shared (transposed), compute norms ----
    #pragma unroll
    for (int r = 0; r < 2; ++r) {
        const int n = tid + r * THREADS;
        const float mv = ms[n];
        const float4* row = reinterpret_cast<const float4*>(xs) + n * 4;
        const float4 v0 = row[0], v1 = row[1], v2 = row[2], v3 = row[3];

        As[ 0][n] = v0.x * mv;  As[ 1][n] = v0.y * mv;
        As[ 2][n] = v0.z * mv;  As[ 3][n] = v0.w * mv;
        As[ 4][n] = v1.x * mv;  As[ 5][n] = v1.y * mv;
        As[ 6][n] = v1.z * mv;  As[ 7][n] = v1.w * mv;
        As[ 8][n] = v2.x * mv;  As[ 9][n] = v2.y * mv;
        As[10][n] = v2.z * mv;  As[11][n] = v2.w * mv;
        As[12][n] = v3.x * mv;  As[13][n] = v3.y * mv;
        As[14][n] = v3.z * mv;  As[15][n] = v3.w * mv;

        float ss = v0.x*v0.x + v0.y*v0.y + v0.z*v0.z + v0.w*v0.w
                 + v1.x*v1.x + v1.y*v1.y + v1.z*v1.z + v1.w*v1.w
                 + v2.x*v2.x + v2.y*v2.y + v2.z*v2.z + v2.w*v2.w
                 + v3.x*v3.x + v3.y*v3.y + v3.z*v3.z + v3.w*v3.w;
        na[n] = ss * mv * mv;
    }
    __syncthreads();

    const int m0 = tx * 4;

    // Per-thread m-side norms (fixed for the whole block).
    float nam[8];
    #pragma unroll
    for (int j = 0; j < 4; ++j) {
        nam[j]     = na[m0 + j];
        nam[4 + j] = na[256 + m0 + j];
    }

    float* outs = out + (size_t)slab * Nn * Nn;

    // 4 iterations x 32 n-rows covers this block's 128-row quarter.
    #pragma unroll 1
    for (int nt = 0; nt < 4; ++nt) {
        const int nb = quad * 128 + nt * 32 + ty * 8;   // 8 consecutive n per thread

        // 8n x 8m tile; f32x2 accumulators paired over adjacent n.
        unsigned long long acc[4][8];
        #pragma unroll
        for (int ip = 0; ip < 4; ++ip)
            #pragma unroll
            for (int j = 0; j < 8; ++j) acc[ip][j] = 0ull;

        #pragma unroll
        for (int f = 0; f < Fd; ++f) {
            // a-side: natural f32 pairs over n (broadcast across warp).
            const ulonglong2* ap = reinterpret_cast<const ulonglong2*>(&As[f][nb]);
            const ulonglong2 aA = ap[0];
            const ulonglong2 aB = ap[1];
            const unsigned long long a4[4] = {aA.x, aA.y, aB.x, aB.y};

            // b-side: 8 m-values, duplicated into both f32x2 lanes.
            const float4 b0 = *reinterpret_cast<const float4*>(&As[f][m0]);
            const float4 b1 = *reinterpret_cast<const float4*>(&As[f][256 + m0]);
            const unsigned long long bd[8] = {
                dup2(b0.x), dup2(b0.y), dup2(b0.z), dup2(b0.w),
                dup2(b1.x), dup2(b1.y), dup2(b1.z), dup2(b1.w)
            };

            #pragma unroll
            for (int ip = 0; ip < 4; ++ip)
                #pragma unroll
                for (int j = 0; j < 8; ++j)
                    acc[ip][j] = fma2(a4[ip], bd[j], acc[ip][j]);
        }

        // ---- Epilogue: d2 = na_n + na_m - 2G -> exp(-0.1 sqrt(max(d2,eps))) ----
        #pragma unroll
        for (int ip = 0; ip < 4; ++ip) {
            const float nn0 = na[nb + 2 * ip];
            const float nn1 = na[nb + 2 * ip + 1];
            float o0[8], o1[8];
            #pragma unroll
            for (int j = 0; j < 8; ++j) {
                const float2 g = unpk(acc[ip][j]);
                const float s0 = nn0 + nam[j];
                const float s1 = nn1 + nam[j];
                const float d20 = fmaxf(fmaf(-2.0f, g.x, s0), EPSV);
                const float d21 = fmaxf(fmaf(-2.0f, g.y, s1), EPSV);
                o0[j] = fminf(ex2_ap(COEF * sqrt_ap(d20)), 1.0f);
                o1[j] = fminf(ex2_ap(COEF * sqrt_ap(d21)), 1.0f);
            }
            float* p0 = outs + (size_t)(nb + 2 * ip) * Nn + m0;
            float* p1 = p0 + Nn;
            *reinterpret_cast<float4*>(p0)       = make_float4(o0[0], o0[1], o0[2], o0[3]);
            *reinterpret_cast<float4*>(p0 + 256) = make_float4(o0[4], o0[5], o0[6], o0[7]);
            *reinterpret_cast<float4*>(p1)       = make_float4(o1[0], o1[1], o1[2], o1[3]);
            *reinterpret_cast<float4*>(p1 + 256) = make_float4(o1[4], o1[5], o1[6], o1[7]);
        }
    }
}

} // anonymous namespace

extern "C" void kernel_launch(void* const* d_in, const int* in_sizes, int n_in,
                              void* d_out, int out_size)
{
    const float* x   = (const float*)d_in[0];   // (8,64,512,16)
    const float* msk = (const float*)d_in[1];   // (8,64,512,1)
    float* out       = (float*)d_out;           // (8,64,512,512,1)

    npg_kernel<<<SLABS * 4, THREADS>>>(x, msk, out);
}

// round 17
// speedup vs baseline: 1.4831x; 1.4831x over previous
#include <cuda_runtime.h>
#include <cstdint>

// NodePairGaussian via tcgen05 tf32 Gram GEMM (sm_103a path) + portable fallback
// for the non-'a' PTX compilation pass (never executed on GB300).
// out[b,k,n,m] = clip(exp(-0.1*sqrt(max(na_n - 2*G_nm + na_m, 1e-6))), 0, 1)
// x (8,64,512,16) f32, msk (8,64,512,1) f32, out (8,64,512,512,1) f32.

namespace {

constexpr int Fd      = 16;
constexpr int Nn      = 512;
constexpr int THREADS = 256;
constexpr float EPSV  = 1e-6f;
constexpr float COEF  = -0.14426950408889634f; // -0.1 * log2(e)

// Dynamic SMEM layout.
constexpr int SM_TMEM  = 0;      // u32 TMEM base ptr (written by tcgen05.alloc)
constexpr int SM_MBAR  = 8;      // mbarrier
constexpr int SM_NA    = 1024;   // 512 f32 squared norms (of tf32-rounded A)
constexpr int SM_AS    = 4096;   // 512 rows x 128B (SW128); reused as transpose bufs
constexpr int SM_TOTAL = SM_AS + Nn * 128;   // 69632 B

constexpr int TMEM_COLS = 256;

#if defined(__CUDA_ARCH_FEAT_SM103_ALL) || defined(__CUDA_ARCH_FEAT_SM100_ALL)
#define NPG_TC 1
#endif

__device__ __forceinline__ uint32_t smem_u32(const void* p) {
    uint32_t a;
    asm("{ .reg .u64 t; cvta.to.shared.u64 t, %1; cvt.u32.u64 %0, t; }" : "=r"(a) : "l"(p));
    return a;
}
__device__ __forceinline__ uint32_t sw128(uint32_t off) { return off ^ ((off >> 3) & 0x70); }

__device__ __forceinline__ float tf32r(float v) {
    uint32_t u;
    asm("cvt.rna.tf32.f32 %0, %1;" : "=r"(u) : "f"(v));
    return __uint_as_float(u);
}
__device__ __forceinline__ float sqrt_ap(float x) {
    float y; asm("sqrt.approx.f32 %0, %1;" : "=f"(y) : "f"(x)); return y;
}
__device__ __forceinline__ float ex2_ap(float x) {
    float y; asm("ex2.approx.f32 %0, %1;" : "=f"(y) : "f"(x)); return y;
}

#ifdef NPG_TC

// idesc: c=F32(1), a=TF32(2), b=TF32(2), K-major both, N=256, M=128
constexpr uint32_t IDESC =
    (1u << 4) | (2u << 7) | (2u << 10) | ((256u / 8) << 17) | ((128u / 16) << 24);

// SW128 K-major smem descriptor base: layout=SW128(2), version=1, SBO=64, LBO=1
constexpr uint64_t DESC_BASE_SW128 =
    (uint64_t(2) << 61) | (uint64_t(1) << 46) | (uint64_t(64) << 32) | (uint64_t(1) << 16);

__device__ __forceinline__ uint32_t elect_one() {
    uint32_t p;
    asm volatile("{ .reg .pred p; elect.sync _|p, 0xFFFFFFFF; selp.b32 %0, 1, 0, p; }" : "=r"(p));
    return p;
}
__device__ __forceinline__ void mma_tf32_ss(uint32_t d, uint64_t a, uint64_t b,
                                            uint32_t idesc, uint32_t en) {
    asm volatile(
        "{\n\t"
        ".reg .pred p;\n\t"
        "setp.ne.u32 p, %5, 0;\n\t"
        "tcgen05.mma.cta_group::1.kind::tf32 [%0], %1, %2, %3, {%4, %4, %4, %4}, p;\n\t"
        "}"
        :: "r"(d), "l"(a), "l"(b), "r"(idesc), "r"(0u), "r"(en) : "memory");
}

#define TC_ALLOC(addr, ncols) \
    asm volatile("tcgen05.alloc.cta_group::1.sync.aligned.shared::cta.b32 [%0], %1;" \
                 :: "r"((uint32_t)(addr)), "r"((uint32_t)(ncols)) : "memory")
#define TC_RELINQ() \
    asm volatile("tcgen05.relinquish_alloc_permit.cta_group::1.sync.aligned;")
#define TC_DEALLOC(tmem, ncols) \
    asm volatile("tcgen05.dealloc.cta_group::1.sync.aligned.b32 %0, %1;" \
                 :: "r"(tmem), "r"((uint32_t)(ncols)))
#define TC_COMMIT(mbar) \
    asm volatile("tcgen05.commit.cta_group::1.mbarrier::arrive::one.shared::cluster.b64 [%0];" \
                 :: "r"((uint32_t)(mbar)) : "memory")
#define TC_FENCE_AFTER()  asm volatile("tcgen05.fence::after_thread_sync;" ::: "memory")
#define TC_FENCE_BEFORE() asm volatile("tcgen05.fence::before_thread_sync;" ::: "memory")
#define TC_WAIT_LD()      asm volatile("tcgen05.wait::ld.sync.aligned;" ::: "memory")
#define MBAR_INIT(mbar, cnt) \
    asm volatile("mbarrier.init.shared.b64 [%0], %1;" \
                 :: "r"((uint32_t)(mbar)), "r"((uint32_t)(cnt)) : "memory")
#define FENCE_ASYNC_SHARED() \
    asm volatile("fence.proxy.async.shared::cta;" ::: "memory")

#define MBAR_WAIT_PARITY(mbar, parity) do {                                        \
    uint32_t _m = (uint32_t)(mbar); uint32_t _p = (uint32_t)(parity);              \
    uint32_t _done;                                                                \
    asm volatile("{\n\t.reg .pred p;\n\t"                                          \
        "mbarrier.try_wait.parity.acquire.cta.shared::cta.b64 p, [%1], %2;\n\t"    \
        "selp.b32 %0, 1, 0, p;\n\t}"                                               \
        : "=r"(_done) : "r"(_m), "r"(_p) : "memory");                              \
    if (!_done) {                                                                  \
        asm volatile("{\n\t.reg .pred P1;\n\t"                                     \
            "WAIT_LOOP_%=:\n\t"                                                    \
            "mbarrier.try_wait.parity.acquire.cta.shared::cta.b64 P1, [%0], %1, 0x989680;\n\t" \
            "@P1 bra.uni WAIT_DONE_%=;\n\t"                                        \
            "bra.uni WAIT_LOOP_%=;\n\t"                                            \
            "WAIT_DONE_%=:\n\t}"                                                   \
            :: "r"(_m), "r"(_p) : "memory");                                       \
    }                                                                              \
} while (0)

#define LDTM_X32(r, addr)                                                          \
    asm volatile("tcgen05.ld.sync.aligned.32x32b.x32.b32 "                         \
        "{%0, %1, %2, %3, %4, %5, %6, %7, "                                        \
        " %8, %9, %10, %11, %12, %13, %14, %15, "                                  \
        " %16, %17, %18, %19, %20, %21, %22, %23, "                                \
        " %24, %25, %26, %27, %28, %29, %30, %31}, [%32];"                         \
        : "=r"((r)[0]),  "=r"((r)[1]),  "=r"((r)[2]),  "=r"((r)[3]),               \
          "=r"((r)[4]),  "=r"((r)[5]),  "=r"((r)[6]),  "=r"((r)[7]),               \
          "=r"((r)[8]),  "=r"((r)[9]),  "=r"((r)[10]), "=r"((r)[11]),              \
          "=r"((r)[12]), "=r"((r)[13]), "=r"((r)[14]), "=r"((r)[15]),              \
          "=r"((r)[16]), "=r"((r)[17]), "=r"((r)[18]), "=r"((r)[19]),              \
          "=r"((r)[20]), "=r"((r)[21]), "=r"((r)[22]), "=r"((r)[23]),              \
          "=r"((r)[24]), "=r"((r)[25]), "=r"((r)[26]), "=r"((r)[27]),              \
          "=r"((r)[28]), "=r"((r)[29]), "=r"((r)[30]), "=r"((r)[31])               \
        : "r"(addr))

#endif // NPG_TC

__global__ __launch_bounds__(THREADS, 2)
void npg_mma(const float* __restrict__ x, const float* __restrict__ msk,
             float* __restrict__ out)
{
    extern __shared__ __align__(1024) char smem[];

    const int tid  = threadIdx.x;
    const int bx   = blockIdx.x;
    const int slab = bx >> 3;          // 0..511
    const int quad = (bx >> 1) & 3;    // n-quarter: rows [quad*128, +128)
    const int half = bx & 1;           // m-half:    cols [half*256, +256)
    const int n0   = quad * 128;
    const int m0   = half * 256;

    float* na_s = reinterpret_cast<float*>(smem + SM_NA);
    const float* xs = x   + (size_t)slab * (Nn * Fd);
    const float* ms = msk + (size_t)slab * Nn;
    float* outs = out + (size_t)slab * Nn * Nn;

#ifdef NPG_TC
    const uint32_t sb = smem_u32(smem);
    const int w    = tid >> 5;
    const int lane = tid & 31;

    // ---- TMEM alloc (warp 0) + mbarrier init ----
    if (w == 0) {
        TC_ALLOC(sb + SM_TMEM, TMEM_COLS);
        TC_RELINQ();
    }
    if (tid == 0) MBAR_INIT(sb + SM_MBAR, 1);

    // ---- Load slab: A = tf32(x*msk) into SW128 SMEM [512 x 128B]; norms of rounded A ----
    #pragma unroll
    for (int r = 0; r < 2; ++r) {
        const int n = tid + r * THREADS;
        const float mv = ms[n];
        const float4* row = reinterpret_cast<const float4*>(xs) + n * 4;
        float acc = 0.0f;
        #pragma unroll
        for (int i = 0; i < 4; ++i) {
            float4 v = row[i];
            float f0 = tf32r(v.x * mv);
            float f1 = tf32r(v.y * mv);
            float f2 = tf32r(v.z * mv);
            float f3 = tf32r(v.w * mv);
            acc += f0 * f0 + f1 * f1 + f2 * f2 + f3 * f3;
            const uint32_t off = sw128((uint32_t)(n * 128 + i * 16));
            *reinterpret_cast<float4*>(smem + SM_AS + off) = make_float4(f0, f1, f2, f3);
        }
        na_s[n] = acc;
    }
    FENCE_ASYNC_SHARED();
    __syncthreads();

    uint32_t tmem;
    asm volatile("ld.shared.b32 %0, [%1];" : "=r"(tmem) : "r"(sb + SM_TMEM));

    // ---- Gram MMA: D[128x256] = A[n0..+128] x A[m0..+256]^T, K=16 as 2 K-steps ----
    if (w == 0) {
        if (elect_one()) {
            const uint64_t a_desc = DESC_BASE_SW128 |
                (((uint64_t)(sb + SM_AS + (uint32_t)n0 * 128) >> 4) & 0x3FFF);
            const uint64_t b_desc = DESC_BASE_SW128 |
                (((uint64_t)(sb + SM_AS + (uint32_t)m0 * 128) >> 4) & 0x3FFF);
            mma_tf32_ss(tmem, a_desc,     b_desc,     IDESC, 0u);  // K[0:8)
            mma_tf32_ss(tmem, a_desc + 2, b_desc + 2, IDESC, 1u);  // K[8:16)
            TC_COMMIT(sb + SM_MBAR);
        }
    }

    MBAR_WAIT_PARITY(sb + SM_MBAR, 0);
    TC_FENCE_AFTER();

    // ---- Epilogue ----
    // Warp w owns n-rows subp*32+lane (subp = w&3) and col group grp*128 (grp = w>>2).
    // Per 32-col chunk: LDTM -> compute -> 32x32 transpose through SMEM (A tile is
    // dead now; reuse it) -> coalesced STG.32 (consecutive lanes = consecutive m).
    const int subp = w & 3;
    const int grp  = w >> 2;
    const int nl   = subp * 32 + lane;
    const float nn = na_s[n0 + nl];
    float* tr = reinterpret_cast<float*>(smem + SM_AS) + w * (32 * 33 + 8);

    #pragma unroll 1
    for (int c = 0; c < 4; ++c) {
        const int col = grp * 128 + c * 32;
        uint32_t r[32];
        LDTM_X32(r, tmem + (uint32_t)col);
        TC_WAIT_LD();

        const int mg = m0 + col;                // global m base of these 32 cols
        float o[32];
        #pragma unroll
        for (int j = 0; j < 32; ++j) {
            const float g  = __uint_as_float(r[j]);
            const float s  = nn + na_s[mg + j];
            const float d2 = fmaxf(fmaf(-2.0f, g, s), EPSV);
            o[j] = ex2_ap(COEF * sqrt_ap(d2));  // <= 1 by construction
        }

        // Transpose: tr[j][lane] = D[row=n0+subp*32+lane][mg+j]  (conflict-free)
        #pragma unroll
        for (int j = 0; j < 32; ++j) tr[j * 33 + lane] = o[j];
        __syncwarp();

        // lane l reads tr[l*33 + i] = D[row i][mg+l] -> coalesced 128B stores.
        float* obase = outs + (size_t)(n0 + subp * 32) * Nn + mg + lane;
        #pragma unroll
        for (int i = 0; i < 32; ++i)
            obase[(size_t)i * Nn] = tr[lane * 33 + i];
        __syncwarp();
    }
    TC_FENCE_BEFORE();

    __syncthreads();
    if (w == 0) TC_DEALLOC(tmem, TMEM_COLS);

#else  // ---------------- portable fallback (non-sm_103a passes only) ----------------
    float* As2 = reinterpret_cast<float*>(smem + SM_AS);  // [512][16], plain layout
    #pragma unroll
    for (int r = 0; r < 2; ++r) {
        const int n = tid + r * THREADS;
        const float mv = ms[n];
        float acc = 0.0f;
        for (int i = 0; i < Fd; ++i) {
            float v = tf32r(xs[n * Fd + i] * mv);
            As2[n * Fd + i] = v;
            acc += v * v;
        }
        na_s[n] = acc;
    }
    __syncthreads();

    for (int idx = tid; idx < 128 * 256; idx += THREADS) {
        const int n = n0 + (idx >> 8);
        const int m = m0 + (idx & 255);
        float g = 0.0f;
        for (int f = 0; f < Fd; ++f) g += As2[n * Fd + f] * As2[m * Fd + f];
        const float d2 = fmaxf(na_s[n] + na_s[m] - 2.0f * g, EPSV);
        outs[(size_t)n * Nn + m] = fminf(ex2_ap(COEF * sqrt_ap(d2)), 1.0f);
    }
#endif
}

} // anonymous namespace

extern "C" void kernel_launch(void* const* d_in, const int* in_sizes, int n_in,
                              void* d_out, int out_size)
{
    const float* x   = (const float*)d_in[0];   // (8,64,512,16)
    const float* msk = (const float*)d_in[1];   // (8,64,512,1)
    float* out       = (float*)d_out;           // (8,64,512,512,1)

    cudaFuncSetAttribute(npg_mma, cudaFuncAttributeMaxDynamicSharedMemorySize, SM_TOTAL);
    npg_mma<<<512 * 8, THREADS, SM_TOTAL>>>(x, msk, out);
}